// round 14
// baseline (speedup 1.0000x reference)
#include <cuda_runtime.h>
#include <cstdint>

// out[n] = S * ( sum_k (x[k]-X_ZP) * y[k,n]  -  Y_ZP * sum_k (x[k]-X_ZP) )
// Exact int32 accumulation. X_SCALE=0.0215, X_ZP=-25, Y_SCALE=0.0176, Y_ZP=18
//
// SINGLE kernel, full-K per block: 512 blocks x 256 thr, block owns 32
// columns x K=8192. Warp = 4 kslices x 8 thr x int4 -> every warp-load is
// 4 FULL 128B lines (R5's proven wavefront cost). The entire shifted x
// vector (32 KB) is preloaded into smem, so the hot loop is LDS + LDG.128
// + IMAD only — no second LDG chain (R13's 6.42 vs 6.83 TB/s gap).
// No partial arrays, no second launch, no inter-block sync.

#define KDIM 8192
#define NDIM 16384
#define THREADS 256
#define KSLICES 32
#define KPER (KDIM / KSLICES)            // 256 rows per thread
#define COLS_PER_BLOCK 32                // 8 threads x int4 = one 128B line
#define NBLOCKS (NDIM / COLS_PER_BLOCK)  // 512

__global__ __launch_bounds__(THREADS, 4) void gemv_fullk_kernel(
    const int* __restrict__ x, const int* __restrict__ y,
    float* __restrict__ out)
{
    __shared__ int  s_a[KDIM];           // 32 KB: a[k] = x[k] + 25
    __shared__ int4 s_red[KSLICES][8];   // per-kslice, per-colgroup partials
    __shared__ int  s_sa[KSLICES];       // per-kslice sum of a
    __shared__ int  s_sum_a;

    const int tid = threadIdx.x;

    // Cooperative preload of x -> smem (8 int4 per thread), shifted by +25.
    {
        const int4* xv = reinterpret_cast<const int4*>(x);
        #pragma unroll
        for (int i = 0; i < KDIM / 4 / THREADS; i++) {
            const int idx = i * THREADS + tid;
            int4 v = __ldg(&xv[idx]);
            v.x += 25;  v.y += 25;  v.z += 25;  v.w += 25;
            *reinterpret_cast<int4*>(&s_a[idx * 4]) = v;
        }
    }
    __syncthreads();

    const int kslice = tid >> 3;         // 0..31
    const int cid    = tid & 7;          // 0..7
    const int col0   = blockIdx.x * COLS_PER_BLOCK + cid * 4;
    const int k0     = kslice * KPER;

    const int4* yp = reinterpret_cast<const int4*>(y + (size_t)k0 * NDIM + col0);
    const size_t strideV = NDIM / 4;

    int a0 = 0, a1 = 0, a2 = 0, a3 = 0;
    int sa = 0;
    #pragma unroll 8
    for (int kk = 0; kk < KPER; kk++) {
        const int a = s_a[k0 + kk];
        const int4 v = __ldcs(&yp[(size_t)kk * strideV]);
        a0 += a * v.x;  a1 += a * v.y;  a2 += a * v.z;  a3 += a * v.w;
        sa += a;
    }

    s_red[kslice][cid] = make_int4(a0, a1, a2, a3);
    if (cid == 0) s_sa[kslice] = sa;
    __syncthreads();

    // zero-point correction: sum of the 32 kslice sums (one warp)
    if (tid < 32) {
        int s = s_sa[tid];
        #pragma unroll
        for (int o = 16; o > 0; o >>= 1)
            s += __shfl_down_sync(0xffffffffu, s, o);
        if (tid == 0) s_sum_a = s;
    }
    __syncthreads();

    // 32 output columns: col c = component (c&3) of colgroup (c>>2).
    if (tid < COLS_PER_BLOCK) {
        const int grp  = tid >> 2;
        const int comp = tid & 3;
        int acc = 0;
        #pragma unroll
        for (int s = 0; s < KSLICES; s++)
            acc += reinterpret_cast<const int*>(&s_red[s][grp])[comp];

        const float S = (float)(0.0215 * 0.0176);
        out[blockIdx.x * COLS_PER_BLOCK + tid] =
            S * (float)(acc - 18 * s_sum_a);
    }
}

extern "C" void kernel_launch(void* const* d_in, const int* in_sizes, int n_in,
                              void* d_out, int out_size) {
    const int* x = (const int*)d_in[0];   // [K]
    const int* y = (const int*)d_in[1];   // [K, N]
    float* out = (float*)d_out;           // [N]

    gemv_fullk_kernel<<<NBLOCKS, THREADS>>>(x, y, out);
}

// round 15
// speedup vs baseline: 1.0242x; 1.0242x over previous
#include <cuda_runtime.h>
#include <cstdint>

// out[n] = S * ( sum_k (x[k]-X_ZP) * y[k,n]  -  Y_ZP * sum_k (x[k]-X_ZP) )
// Exact int32 accumulation. X_SCALE=0.0215, X_ZP=-25, Y_SCALE=0.0176, Y_ZP=18
//
// SINGLE kernel, 2-CTA clusters. Each cluster owns 32 output columns;
// rank r streams K[r*4096,(r+1)*4096) with the proven layout (32 kslices x
// 8 thr x int4 -> every warp-load = 4 FULL 128B lines). Grid = 1024 CTAs
// (~1% wave imbalance at occ 8, vs 15% for the 512-block R13/R14 variants).
// Combine: rank 1 sends 32 col-partials + its sum_a to rank 0's smem via
// mapa + st.shared::cluster; barrier.cluster (release/acquire) orders it;
// rank 0 adds + stores fp32. No global partials, no second launch.

#define KDIM 8192
#define NDIM 16384
#define THREADS 256
#define KHALF (KDIM / 2)                  // 4096 per CTA
#define KSLICES 32
#define KPER (KHALF / KSLICES)            // 128 rows per thread
#define COLS_PER_BLOCK 32
#define NTILES (NDIM / COLS_PER_BLOCK)    // 512 clusters
#define NBLOCKS (NTILES * 2)              // 1024 CTAs

__device__ __forceinline__ uint32_t smem_u32(const void* p) {
    uint32_t a;
    asm("{ .reg .u64 t; cvta.to.shared.u64 t, %1; cvt.u32.u64 %0, t; }"
        : "=r"(a) : "l"(p));
    return a;
}

__global__ __launch_bounds__(THREADS, 8) __cluster_dims__(2, 1, 1)
void gemv_cluster_kernel(
    const int* __restrict__ x, const int* __restrict__ y,
    float* __restrict__ out)
{
    __shared__ int  s_a[KHALF];           // 16 KB: a[k]=x[k]+25 (this half)
    __shared__ int4 s_red[KSLICES][8];    // 4 KB per-kslice partials
    __shared__ int  s_sa[KSLICES];
    __shared__ int  s_recv[COLS_PER_BLOCK + 1];  // peer partials + peer sum_a

    const int tid = threadIdx.x;
    uint32_t rank;
    asm("mov.u32 %0, %%cluster_ctarank;" : "=r"(rank));
    const int tile   = blockIdx.x >> 1;
    const int k0cta  = (int)rank * KHALF;

    // Preload this CTA's x half -> smem (4 int4 per thread), shifted +25.
    {
        const int4* xv = reinterpret_cast<const int4*>(x + k0cta);
        #pragma unroll
        for (int i = 0; i < KHALF / 4 / THREADS; i++) {
            const int idx = i * THREADS + tid;
            int4 v = __ldg(&xv[idx]);
            v.x += 25;  v.y += 25;  v.z += 25;  v.w += 25;
            *reinterpret_cast<int4*>(&s_a[idx * 4]) = v;
        }
    }
    __syncthreads();

    const int kslice = tid >> 3;          // 0..31
    const int cid    = tid & 7;           // 0..7 (8 x 16B = one 128B line)
    const int col0   = tile * COLS_PER_BLOCK + cid * 4;
    const int k0     = kslice * KPER;

    const int4* yp = reinterpret_cast<const int4*>(
        y + (size_t)(k0cta + k0) * NDIM + col0);
    const size_t strideV = NDIM / 4;

    int a0 = 0, a1 = 0, a2 = 0, a3 = 0;
    int sa = 0;
    #pragma unroll 8
    for (int kk = 0; kk < KPER; kk++) {
        const int a = s_a[k0 + kk];
        const int4 v = __ldcs(&yp[(size_t)kk * strideV]);
        a0 += a * v.x;  a1 += a * v.y;  a2 += a * v.z;  a3 += a * v.w;
        sa += a;
    }

    s_red[kslice][cid] = make_int4(a0, a1, a2, a3);
    if (cid == 0) s_sa[kslice] = sa;
    __syncthreads();

    // Per-CTA reduce: thread tid<32 owns column tid; also reduce sum_a.
    int acc = 0, suma = 0;
    if (tid < 32) {
        const int grp  = tid >> 2;
        const int comp = tid & 3;
        #pragma unroll
        for (int s = 0; s < KSLICES; s++)
            acc += reinterpret_cast<const int*>(&s_red[s][grp])[comp];

        int t = s_sa[tid];
        #pragma unroll
        for (int o = 16; o > 0; o >>= 1)
            t += __shfl_down_sync(0xffffffffu, t, o);
        suma = __shfl_sync(0xffffffffu, t, 0);   // broadcast half-sum
    }

    // rank 1 -> rank 0: 32 partials + sum_a via DSMEM.
    if (rank == 1 && tid < 32) {
        uint32_t la = smem_u32(&s_recv[tid]);
        uint32_t ra;
        asm("mapa.shared::cluster.u32 %0, %1, %2;" : "=r"(ra) : "r"(la), "r"(0));
        asm volatile("st.shared::cluster.u32 [%0], %1;" :: "r"(ra), "r"(acc) : "memory");
        if (tid == 0) {
            uint32_t la2 = smem_u32(&s_recv[COLS_PER_BLOCK]);
            uint32_t ra2;
            asm("mapa.shared::cluster.u32 %0, %1, %2;" : "=r"(ra2) : "r"(la2), "r"(0));
            asm volatile("st.shared::cluster.u32 [%0], %1;" :: "r"(ra2), "r"(suma) : "memory");
        }
    }

    // Cluster barrier: arrive = release (orders DSMEM stores), wait = acquire.
    asm volatile("barrier.cluster.arrive.aligned;" ::: "memory");
    asm volatile("barrier.cluster.wait.aligned;" ::: "memory");

    if (rank == 0 && tid < 32) {
        const int total   = acc + s_recv[tid];
        const int sum_a   = suma + s_recv[COLS_PER_BLOCK];
        const float S = (float)(0.0215 * 0.0176);
        out[tile * COLS_PER_BLOCK + tid] = S * (float)(total - 18 * sum_a);
    }
}

extern "C" void kernel_launch(void* const* d_in, const int* in_sizes, int n_in,
                              void* d_out, int out_size) {
    const int* x = (const int*)d_in[0];   // [K]
    const int* y = (const int*)d_in[1];   // [K, N]
    float* out = (float*)d_out;           // [N]

    gemv_cluster_kernel<<<NBLOCKS, THREADS>>>(x, y, out);
}

// round 17
// speedup vs baseline: 1.0554x; 1.0304x over previous
#include <cuda_runtime.h>
#include <cstdint>

// out[n] = S * ( sum_k (x[k]-X_ZP) * y[k,n]  -  Y_ZP * sum_k (x[k]-X_ZP) )
// Exact int32 accumulation. X_SCALE=0.0215, X_ZP=-25, Y_SCALE=0.0176, Y_ZP=18
//
// R5 structure (best measured: gemv 75.0us @ 6.83 TB/s):
//   gemv:     (16 n-tiles x 64 K-splits) x 256 thr, int4 __ldcs stream.
//             Partials stored via createpolicy(evict_last)+st.cache_hint so
//             the 4 MB partial array survives the 512 MB y-stream in L2
//             (plain stores got evicted: R5 finalize showed 3.2 MB of DRAM
//             misses). 16B stores need the cache_hint form — the direct
//             .L2::evict_last modifier only encodes on 32B stores.
//   finalize: 256 blocks x 256 thr, 4 thr/col x 16 splits, smem combine,
//             loads with the same evict_last policy (L2 hits).

#define KDIM 8192
#define NDIM 16384
#define THREADS 256
#define COLS_PER_THREAD 4
#define COLS_PER_BLOCK (THREADS * COLS_PER_THREAD)    // 1024
#define N_TILES (NDIM / COLS_PER_BLOCK)               // 16
#define KCHUNK 128
#define SPLITS (KDIM / KCHUNK)                        // 64

#define FIN_THREADS 256
#define FIN_COLS 64                                   // columns per block
#define FIN_QUARTERS 4                                // threads per column
#define FIN_SPLITS_PER_THREAD (SPLITS / FIN_QUARTERS) // 16
#define FIN_BLOCKS (NDIM / FIN_COLS)                  // 256

__device__ int g_part[SPLITS][NDIM];   // per-split partial dot products
__device__ int g_sa_part[SPLITS];      // per-split sum of (x[k]+25)

__device__ __forceinline__ uint64_t evict_last_policy() {
    uint64_t pol;
    asm("createpolicy.fractional.L2::evict_last.b64 %0, 1.0;" : "=l"(pol));
    return pol;
}

__device__ __forceinline__ void st_hint_int4(int* p, int a, int b, int c, int d,
                                             uint64_t pol) {
    asm volatile("st.global.L2::cache_hint.v4.s32 [%0], {%1,%2,%3,%4}, %5;"
                 :: "l"(p), "r"(a), "r"(b), "r"(c), "r"(d), "l"(pol) : "memory");
}

__device__ __forceinline__ int ld_hint_int(const int* p, uint64_t pol) {
    int v;
    asm volatile("ld.global.L2::cache_hint.s32 %0, [%1], %2;"
                 : "=r"(v) : "l"(p), "l"(pol) : "memory");
    return v;
}

__global__ __launch_bounds__(THREADS) void gemv_kernel(
    const int* __restrict__ x, const int* __restrict__ y)
{
    __shared__ int sa[KCHUNK];
    const int tid   = threadIdx.x;
    const int split = blockIdx.y;
    const int k0    = split * KCHUNK;

    // a[k] = x[k] - X_ZP = x[k] + 25
    if (tid < KCHUNK)
        sa[tid] = x[k0 + tid] + 25;
    __syncthreads();

    const int n0 = blockIdx.x * COLS_PER_BLOCK + tid * COLS_PER_THREAD;
    const int4* yp = reinterpret_cast<const int4*>(y + (size_t)k0 * NDIM + n0);
    const size_t strideV = NDIM / 4;

    int a0 = 0, a1 = 0, a2 = 0, a3 = 0;
    #pragma unroll 8
    for (int kk = 0; kk < KCHUNK; kk++) {
        const int a = sa[kk];
        const int4 v = __ldcs(&yp[(size_t)kk * strideV]);
        a0 += a * v.x;  a1 += a * v.y;  a2 += a * v.z;  a3 += a * v.w;
    }

    st_hint_int4(&g_part[split][n0], a0, a1, a2, a3, evict_last_policy());

    // one n-tile per split contributes the sum-of-a partial
    if (blockIdx.x == 0 && tid < 32) {
        int s = 0;
        #pragma unroll
        for (int i = 0; i < KCHUNK / 32; i++)
            s += sa[tid + i * 32];
        #pragma unroll
        for (int o = 16; o > 0; o >>= 1)
            s += __shfl_down_sync(0xffffffffu, s, o);
        if (tid == 0) g_sa_part[split] = s;
    }
}

__global__ __launch_bounds__(FIN_THREADS) void finalize_kernel(float* __restrict__ out) {
    __shared__ int s_red[FIN_QUARTERS][FIN_COLS];
    __shared__ int s_sa;

    const int tid   = threadIdx.x;
    const int lane  = tid & (FIN_COLS - 1);
    const int col   = blockIdx.x * FIN_COLS + lane;
    const int q     = tid >> 6;                 // 0..3
    const int sbase = q * FIN_SPLITS_PER_THREAD;
    const uint64_t pol = evict_last_policy();

    if (tid < 32) {
        int s = g_sa_part[tid] + g_sa_part[tid + 32];
        #pragma unroll
        for (int o = 16; o > 0; o >>= 1)
            s += __shfl_down_sync(0xffffffffu, s, o);
        if (tid == 0) s_sa = s;
    }

    // 16 independent coalesced loads per thread (L2-hit after evict_last).
    int r0 = 0, r1 = 0, r2 = 0, r3 = 0;
    #pragma unroll
    for (int i = 0; i < FIN_SPLITS_PER_THREAD; i += 4) {
        r0 += ld_hint_int(&g_part[sbase + i + 0][col], pol);
        r1 += ld_hint_int(&g_part[sbase + i + 1][col], pol);
        r2 += ld_hint_int(&g_part[sbase + i + 2][col], pol);
        r3 += ld_hint_int(&g_part[sbase + i + 3][col], pol);
    }
    s_red[q][lane] = (r0 + r1) + (r2 + r3);
    __syncthreads();

    if (tid < FIN_COLS) {
        const int acc = (s_red[0][tid] + s_red[1][tid]) +
                        (s_red[2][tid] + s_red[3][tid]);
        const float S = (float)(0.0215 * 0.0176);
        out[blockIdx.x * FIN_COLS + tid] = S * (float)(acc - 18 * s_sa);
    }
}

extern "C" void kernel_launch(void* const* d_in, const int* in_sizes, int n_in,
                              void* d_out, int out_size) {
    const int* x = (const int*)d_in[0];   // [K]
    const int* y = (const int*)d_in[1];   // [K, N]
    float* out = (float*)d_out;           // [N]

    dim3 grid(N_TILES, SPLITS);
    gemv_kernel<<<grid, THREADS>>>(x, y);
    finalize_kernel<<<FIN_BLOCKS, FIN_THREADS>>>(out);
}